// round 1
// baseline (speedup 1.0000x reference)
#include <cuda_runtime.h>
#include <math.h>

// Problem dims (fixed)
#define BZ 4
#define SQ 2048
#define DM 1024
#define NH 16
#define HD 64
#define MROWS (BZ * SQ)   // 8192

// ---------------- scratch (device globals; no runtime alloc allowed) --------
__device__ float g_q[(size_t)MROWS * DM];
__device__ float g_k[(size_t)MROWS * DM];
__device__ float g_v[(size_t)MROWS * DM];
__device__ float g_attn[(size_t)MROWS * DM];
__device__ float g_y[(size_t)MROWS * DM];

// ---------------- SGEMM: C = A[MxK] @ B[KxN] + bias[N] (+ residual[MxN]) ----
// 128x128 block tile, BK=8, 256 threads, 8x8 per thread (2x2 of 4x4 micro).
__global__ __launch_bounds__(256) void sgemm128(
    const float* __restrict__ A, const float* __restrict__ Bm,
    const float* __restrict__ bias, const float* __restrict__ res,
    float* __restrict__ C, int M, int N, int K)
{
    __shared__ float As[8][128];   // [k][m] (transposed on store)
    __shared__ float Bs[8][128];   // [k][n]

    const int tid = threadIdx.x;
    const int bm = blockIdx.y * 128;
    const int bn = blockIdx.x * 128;
    const int tx = tid & 15;       // 0..15 -> N
    const int ty = tid >> 4;       // 0..15 -> M

    const int arow = tid >> 1;            // 0..127
    const int acol = (tid & 1) << 2;      // 0 or 4
    const int brow = tid >> 5;            // 0..7
    const int bcol = (tid & 31) << 2;     // 0..124

    const float* Ag = A + (size_t)(bm + arow) * K + acol;
    const float* Bg = Bm + (size_t)brow * N + bn + bcol;

    float acc[8][8];
#pragma unroll
    for (int i = 0; i < 8; ++i)
#pragma unroll
        for (int j = 0; j < 8; ++j) acc[i][j] = 0.f;

    for (int k0 = 0; k0 < K; k0 += 8) {
        float4 av = *(const float4*)(Ag + k0);
        float4 bv = *(const float4*)(Bg + (size_t)k0 * N);
        As[acol + 0][arow] = av.x;
        As[acol + 1][arow] = av.y;
        As[acol + 2][arow] = av.z;
        As[acol + 3][arow] = av.w;
        *(float4*)&Bs[brow][bcol] = bv;
        __syncthreads();

#pragma unroll
        for (int kk = 0; kk < 8; ++kk) {
            float4 a0 = *(const float4*)&As[kk][ty << 2];
            float4 a1 = *(const float4*)&As[kk][(ty << 2) + 64];
            float4 b0 = *(const float4*)&Bs[kk][tx << 2];
            float4 b1 = *(const float4*)&Bs[kk][(tx << 2) + 64];
            float ar[8] = {a0.x, a0.y, a0.z, a0.w, a1.x, a1.y, a1.z, a1.w};
            float br[8] = {b0.x, b0.y, b0.z, b0.w, b1.x, b1.y, b1.z, b1.w};
#pragma unroll
            for (int i = 0; i < 8; ++i)
#pragma unroll
                for (int j = 0; j < 8; ++j)
                    acc[i][j] = fmaf(ar[i], br[j], acc[i][j]);
        }
        __syncthreads();
    }

    // epilogue
#pragma unroll
    for (int ih = 0; ih < 2; ++ih) {
#pragma unroll
        for (int i2 = 0; i2 < 4; ++i2) {
            int i = ih * 4 + i2;
            int r = bm + ih * 64 + (ty << 2) + i2;
#pragma unroll
            for (int jh = 0; jh < 2; ++jh) {
                int c = bn + jh * 64 + (tx << 2);
                float4 bb = *(const float4*)&bias[c];
                float4 o;
                o.x = acc[i][jh * 4 + 0] + bb.x;
                o.y = acc[i][jh * 4 + 1] + bb.y;
                o.z = acc[i][jh * 4 + 2] + bb.z;
                o.w = acc[i][jh * 4 + 3] + bb.w;
                if (res) {
                    float4 rr = *(const float4*)&res[(size_t)r * N + c];
                    o.x += rr.x; o.y += rr.y; o.z += rr.z; o.w += rr.w;
                }
                *(float4*)&C[(size_t)r * N + c] = o;
            }
        }
    }
}

// ---------------- Flash attention (fp32, causal) ----------------------------
// One block per (q-tile of 64, head, batch). 256 threads (16x16), 4x4 micro.
// Dynamic smem: Qt[64][64] (d-major), Kt[64][64] (d-major), Vs[64][64], Ps[64][64].
__global__ __launch_bounds__(256) void flash_attn(
    const float* __restrict__ q, const float* __restrict__ k,
    const float* __restrict__ v, float* __restrict__ o)
{
    extern __shared__ float sm[];
    float* Qt = sm;             // [d][r]
    float* Kt = sm + 4096;      // [d][c]
    float* Vs = sm + 8192;      // [c][d]
    float* Ps = sm + 12288;     // [r][c]

    const int tid = threadIdx.x;
    const int tx = tid & 15;    // key/dv cols
    const int ty = tid >> 4;    // q rows
    const int qt = blockIdx.x;
    const int h  = blockIdx.y;
    const int b  = blockIdx.z;
    const int q0 = qt * 64;
    const size_t base = (size_t)b * SQ * DM + (size_t)h * HD;

    const int lrow = tid >> 2;          // 0..63
    const int lcol = (tid & 3) << 4;    // 0,16,32,48

    // load Q (transposed, pre-scaled by 1/sqrt(HD)=0.125)
    {
        const float* qp = q + base + (size_t)(q0 + lrow) * DM + lcol;
#pragma unroll
        for (int u = 0; u < 4; ++u) {
            float4 t = *(const float4*)(qp + 4 * u);
            int d = lcol + 4 * u;
            Qt[(d + 0) * 64 + lrow] = t.x * 0.125f;
            Qt[(d + 1) * 64 + lrow] = t.y * 0.125f;
            Qt[(d + 2) * 64 + lrow] = t.z * 0.125f;
            Qt[(d + 3) * 64 + lrow] = t.w * 0.125f;
        }
    }

    float m_i[4], l_i[4], acc[4][4];
#pragma unroll
    for (int i = 0; i < 4; ++i) {
        m_i[i] = -1e30f; l_i[i] = 0.f;
#pragma unroll
        for (int j = 0; j < 4; ++j) acc[i][j] = 0.f;
    }

    for (int kt = 0; kt <= qt; ++kt) {
        __syncthreads();   // guards Q load (iter 0) + previous-iter smem reads
        {
            const float* kp = k + base + (size_t)(kt * 64 + lrow) * DM + lcol;
            const float* vp = v + base + (size_t)(kt * 64 + lrow) * DM + lcol;
#pragma unroll
            for (int u = 0; u < 4; ++u) {
                float4 t = *(const float4*)(kp + 4 * u);
                int d = lcol + 4 * u;
                Kt[(d + 0) * 64 + lrow] = t.x;
                Kt[(d + 1) * 64 + lrow] = t.y;
                Kt[(d + 2) * 64 + lrow] = t.z;
                Kt[(d + 3) * 64 + lrow] = t.w;
                float4 w = *(const float4*)(vp + 4 * u);
                *(float4*)&Vs[lrow * 64 + d] = w;
            }
        }
        __syncthreads();

        // S = Q @ K^T  (4x4 per thread)
        float s[4][4];
#pragma unroll
        for (int i = 0; i < 4; ++i)
#pragma unroll
            for (int j = 0; j < 4; ++j) s[i][j] = 0.f;

#pragma unroll 16
        for (int d = 0; d < 64; ++d) {
            float4 qv = *(const float4*)&Qt[d * 64 + (ty << 2)];
            float4 kv = *(const float4*)&Kt[d * 64 + (tx << 2)];
            float qa[4] = {qv.x, qv.y, qv.z, qv.w};
            float ka[4] = {kv.x, kv.y, kv.z, kv.w};
#pragma unroll
            for (int i = 0; i < 4; ++i)
#pragma unroll
                for (int j = 0; j < 4; ++j)
                    s[i][j] = fmaf(qa[i], ka[j], s[i][j]);
        }

        if (kt == qt) {   // diagonal tile: causal mask
#pragma unroll
            for (int i = 0; i < 4; ++i)
#pragma unroll
                for (int j = 0; j < 4; ++j)
                    if ((tx * 4 + j) > (ty * 4 + i)) s[i][j] = -1e30f;
        }

        // online softmax per row (row owned by the 16 tx-threads of this ty)
#pragma unroll
        for (int i = 0; i < 4; ++i) {
            float tm = fmaxf(fmaxf(s[i][0], s[i][1]), fmaxf(s[i][2], s[i][3]));
            tm = fmaxf(tm, __shfl_xor_sync(0xffffffffu, tm, 1));
            tm = fmaxf(tm, __shfl_xor_sync(0xffffffffu, tm, 2));
            tm = fmaxf(tm, __shfl_xor_sync(0xffffffffu, tm, 4));
            tm = fmaxf(tm, __shfl_xor_sync(0xffffffffu, tm, 8));
            float mn = fmaxf(m_i[i], tm);
            float al = __expf(m_i[i] - mn);
            float p0 = __expf(s[i][0] - mn);
            float p1 = __expf(s[i][1] - mn);
            float p2 = __expf(s[i][2] - mn);
            float p3 = __expf(s[i][3] - mn);
            s[i][0] = p0; s[i][1] = p1; s[i][2] = p2; s[i][3] = p3;
            float rs = p0 + p1 + p2 + p3;
            rs += __shfl_xor_sync(0xffffffffu, rs, 1);
            rs += __shfl_xor_sync(0xffffffffu, rs, 2);
            rs += __shfl_xor_sync(0xffffffffu, rs, 4);
            rs += __shfl_xor_sync(0xffffffffu, rs, 8);
            l_i[i] = l_i[i] * al + rs;
            m_i[i] = mn;
#pragma unroll
            for (int j = 0; j < 4; ++j) acc[i][j] *= al;
        }

        // stage P to smem (natural [r][c], float4 stores, conflict-free)
#pragma unroll
        for (int i = 0; i < 4; ++i)
            *(float4*)&Ps[(ty * 4 + i) * 64 + (tx << 2)] =
                make_float4(s[i][0], s[i][1], s[i][2], s[i][3]);
        __syncthreads();

        // O += P @ V
#pragma unroll 4
        for (int c0 = 0; c0 < 64; c0 += 4) {
            float pr[4][4];
#pragma unroll
            for (int i = 0; i < 4; ++i) {
                float4 t = *(const float4*)&Ps[(ty * 4 + i) * 64 + c0];
                pr[i][0] = t.x; pr[i][1] = t.y; pr[i][2] = t.z; pr[i][3] = t.w;
            }
#pragma unroll
            for (int cc = 0; cc < 4; ++cc) {
                float4 vv = *(const float4*)&Vs[(c0 + cc) * 64 + (tx << 2)];
                float va[4] = {vv.x, vv.y, vv.z, vv.w};
#pragma unroll
                for (int i = 0; i < 4; ++i)
#pragma unroll
                    for (int j = 0; j < 4; ++j)
                        acc[i][j] = fmaf(pr[i][cc], va[j], acc[i][j]);
            }
        }
    }

    // write output rows
#pragma unroll
    for (int i = 0; i < 4; ++i) {
        float inv = 1.f / l_i[i];
        float4 ov = make_float4(acc[i][0] * inv, acc[i][1] * inv,
                                acc[i][2] * inv, acc[i][3] * inv);
        *(float4*)&o[base + (size_t)(q0 + ty * 4 + i) * DM + (tx << 2)] = ov;
    }
}

// ---------------- LayerNorm over rows of y[MROWS][DM] ------------------------
__global__ __launch_bounds__(256) void ln_kernel(
    const float* __restrict__ y, const float* __restrict__ g,
    const float* __restrict__ bta, float* __restrict__ out)
{
    const int row = blockIdx.x;
    const int tid = threadIdx.x;
    const float* yr = y + (size_t)row * DM;

    float4 vv = *(const float4*)(yr + tid * 4);
    float s  = vv.x + vv.y + vv.z + vv.w;
    float sq = vv.x * vv.x + vv.y * vv.y + vv.z * vv.z + vv.w * vv.w;

#pragma unroll
    for (int off = 16; off > 0; off >>= 1) {
        s  += __shfl_xor_sync(0xffffffffu, s, off);
        sq += __shfl_xor_sync(0xffffffffu, sq, off);
    }
    __shared__ float ssum[8], ssq[8];
    if ((tid & 31) == 0) { ssum[tid >> 5] = s; ssq[tid >> 5] = sq; }
    __syncthreads();
    __shared__ float mu_s, rs_s;
    if (tid == 0) {
        float ts = 0.f, tq = 0.f;
#pragma unroll
        for (int i = 0; i < 8; ++i) { ts += ssum[i]; tq += ssq[i]; }
        float mu = ts * (1.f / DM);
        float var = tq * (1.f / DM) - mu * mu;
        mu_s = mu;
        rs_s = rsqrtf(var + 1e-5f);
    }
    __syncthreads();
    float mu = mu_s, rstd = rs_s;

    float4 gg = *(const float4*)(g + tid * 4);
    float4 bb = *(const float4*)(bta + tid * 4);
    float4 o;
    o.x = (vv.x - mu) * rstd * gg.x + bb.x;
    o.y = (vv.y - mu) * rstd * gg.y + bb.y;
    o.z = (vv.z - mu) * rstd * gg.z + bb.z;
    o.w = (vv.w - mu) * rstd * gg.w + bb.w;
    *(float4*)&out[(size_t)row * DM + tid * 4] = o;
}

// ---------------- launch -----------------------------------------------------
extern "C" void kernel_launch(void* const* d_in, const int* in_sizes, int n_in,
                              void* d_out, int out_size)
{
    const float* x  = (const float*)d_in[0];
    const float* Wq = (const float*)d_in[1];
    const float* bq = (const float*)d_in[2];
    const float* Wk = (const float*)d_in[3];
    const float* bk = (const float*)d_in[4];
    const float* Wv = (const float*)d_in[5];
    const float* bv = (const float*)d_in[6];
    const float* Wp = (const float*)d_in[7];
    const float* bp = (const float*)d_in[8];
    const float* lg = (const float*)d_in[9];
    const float* lb = (const float*)d_in[10];
    float* out = (float*)d_out;

    float *q, *k, *v, *attn, *y;
    cudaGetSymbolAddress((void**)&q, g_q);
    cudaGetSymbolAddress((void**)&k, g_k);
    cudaGetSymbolAddress((void**)&v, g_v);
    cudaGetSymbolAddress((void**)&attn, g_attn);
    cudaGetSymbolAddress((void**)&y, g_y);

    dim3 gg(DM / 128, MROWS / 128);  // (8, 64)
    sgemm128<<<gg, 256>>>(x, Wq, bq, nullptr, q, MROWS, DM, DM);
    sgemm128<<<gg, 256>>>(x, Wk, bk, nullptr, k, MROWS, DM, DM);
    sgemm128<<<gg, 256>>>(x, Wv, bv, nullptr, v, MROWS, DM, DM);

    cudaFuncSetAttribute(flash_attn, cudaFuncAttributeMaxDynamicSharedMemorySize,
                         64 * 1024);
    flash_attn<<<dim3(SQ / 64, NH, BZ), 256, 64 * 1024>>>(q, k, v, attn);

    sgemm128<<<gg, 256>>>(attn, Wp, bp, x, y, MROWS, DM, DM);
    ln_kernel<<<MROWS, 256>>>(y, lg, lb, out);
}

// round 2
// speedup vs baseline: 2.1073x; 2.1073x over previous
#include <cuda_runtime.h>
#include <math.h>
#include <stdint.h>

// Problem dims (fixed)
#define BZ 4
#define SQ 2048
#define DM 1024
#define NH 16
#define HD 64
#define MROWS (BZ * SQ)   // 8192

// ---------------- scratch (device globals; no runtime alloc allowed) --------
__device__ float g_q[(size_t)MROWS * DM];
__device__ float g_k[(size_t)MROWS * DM];
__device__ float g_v[(size_t)MROWS * DM];
__device__ float g_attn[(size_t)MROWS * DM];
__device__ float g_y[(size_t)MROWS * DM];
__device__ float g_xr[(size_t)MROWS * DM];
__device__ float g_wq[(size_t)DM * DM];
__device__ float g_wk[(size_t)DM * DM];
__device__ float g_wv[(size_t)DM * DM];
__device__ float g_wp[(size_t)DM * DM];

// ---------------- helpers ----------------------------------------------------
__device__ __forceinline__ float tf32r(float x) {
    uint32_t u;
    asm("cvt.rna.tf32.f32 %0, %1;" : "=r"(u) : "f"(x));
    return __uint_as_float(u);
}

#define MMA_TF32(d, a, b)                                                  \
    asm volatile(                                                          \
        "mma.sync.aligned.m16n8k8.row.col.f32.tf32.tf32.f32 "              \
        "{%0,%1,%2,%3}, {%4,%5,%6,%7}, {%8,%9}, {%0,%1,%2,%3};\n"          \
        : "+f"((d)[0]), "+f"((d)[1]), "+f"((d)[2]), "+f"((d)[3])           \
        : "r"((a)[0]), "r"((a)[1]), "r"((a)[2]), "r"((a)[3]),              \
          "r"((b)[0]), "r"((b)[1]))

#define CP_ASYNC16(dst_u32, src_ptr)                                       \
    asm volatile("cp.async.ca.shared.global [%0], [%1], 16;\n" ::          \
                 "r"(dst_u32), "l"(src_ptr))

// ---------------- elementwise tf32 rounding ----------------------------------
__global__ __launch_bounds__(256) void round_tf32_k(
    const float* __restrict__ in, float* __restrict__ out, int n4)
{
    int i = blockIdx.x * blockDim.x + threadIdx.x;
    if (i < n4) {
        float4 t = ((const float4*)in)[i];
        t.x = tf32r(t.x); t.y = tf32r(t.y);
        t.z = tf32r(t.z); t.w = tf32r(t.w);
        ((float4*)out)[i] = t;
    }
}

// ---------------- TF32 tensor-core GEMM --------------------------------------
// C[M,N] = A[M,K] @ B[K,N] + bias (+ res).  A,B pre-rounded to tf32 values.
// 128x128x32 tile, 256 threads, warp tile 64x32 (4x4 m16n8k8 atoms).
#define GBM 128
#define GBN 128
#define GBK 32
#define ASTR 36        // 32 + 4 pad -> conflict-free A frag loads
#define BSTR 136       // 128 + 8 pad -> conflict-free B frag loads
#define ASZ (GBM * ASTR)   // floats
#define BSZ (GBK * BSTR)
#define GEMM_SMEM ((2 * (ASZ + BSZ)) * 4)

__global__ __launch_bounds__(256) void gemm_tf32(
    const float* __restrict__ A, const float* __restrict__ B,
    const float* __restrict__ bias, const float* __restrict__ res,
    float* __restrict__ C, int K, int N, int round_out)
{
    extern __shared__ float sm[];
    float* AsBuf[2] = { sm, sm + ASZ };
    float* BsBuf[2] = { sm + 2 * ASZ, sm + 2 * ASZ + BSZ };
    const uint32_t smem_u = (uint32_t)__cvta_generic_to_shared(sm);

    const int tid = threadIdx.x;
    const int bm = blockIdx.y * GBM;
    const int bn = blockIdx.x * GBN;
    const int warp = tid >> 5, lane = tid & 31;
    const int gid = lane >> 2, tig = lane & 3;
    const int wm = warp >> 2;      // 0..1 -> 64 rows each
    const int wn = warp & 3;       // 0..3 -> 32 cols each

    const int aRow = tid >> 3;           // 0..31
    const int aCol = (tid & 7) * 4;      // 0..28
    const int bRow = tid >> 5;           // 0..7
    const int bCol = (tid & 31) * 4;     // 0..124

    float acc[4][4][4];
#pragma unroll
    for (int i = 0; i < 4; ++i)
#pragma unroll
        for (int j = 0; j < 4; ++j)
#pragma unroll
            for (int l = 0; l < 4; ++l) acc[i][j][l] = 0.f;

    auto load_tile = [&](int stage, int k0) {
        uint32_t aB = smem_u + (uint32_t)(stage * ASZ) * 4u;
        uint32_t bB = smem_u + (uint32_t)(2 * ASZ + stage * BSZ) * 4u;
        const float* Ap = A + (size_t)(bm + aRow) * K + k0 + aCol;
#pragma unroll
        for (int i = 0; i < 4; ++i)
            CP_ASYNC16(aB + (uint32_t)(((aRow + 32 * i) * ASTR + aCol) * 4),
                       Ap + (size_t)(32 * i) * K);
        const float* Bp = B + (size_t)(k0 + bRow) * N + bn + bCol;
#pragma unroll
        for (int i = 0; i < 4; ++i)
            CP_ASYNC16(bB + (uint32_t)(((bRow + 8 * i) * BSTR + bCol) * 4),
                       Bp + (size_t)(8 * i) * N);
        asm volatile("cp.async.commit_group;\n" ::);
    };

    const int nk = K / GBK;
    load_tile(0, 0);

    for (int t = 0; t < nk; ++t) {
        if (t + 1 < nk) {
            load_tile((t + 1) & 1, (t + 1) * GBK);
            asm volatile("cp.async.wait_group 1;\n" ::);
        } else {
            asm volatile("cp.async.wait_group 0;\n" ::);
        }
        __syncthreads();

        const float* Asp = AsBuf[t & 1];
        const float* Bsp = BsBuf[t & 1];

#pragma unroll
        for (int kk = 0; kk < 4; ++kk) {
            uint32_t a[4][4], bf[4][2];
            const int c = kk * 8 + tig;
#pragma unroll
            for (int ma = 0; ma < 4; ++ma) {
                const int r = wm * 64 + ma * 16 + gid;
                a[ma][0] = __float_as_uint(Asp[r * ASTR + c]);
                a[ma][1] = __float_as_uint(Asp[(r + 8) * ASTR + c]);
                a[ma][2] = __float_as_uint(Asp[r * ASTR + c + 4]);
                a[ma][3] = __float_as_uint(Asp[(r + 8) * ASTR + c + 4]);
            }
#pragma unroll
            for (int na = 0; na < 4; ++na) {
                const int n = wn * 32 + na * 8 + gid;
                bf[na][0] = __float_as_uint(Bsp[c * BSTR + n]);
                bf[na][1] = __float_as_uint(Bsp[(c + 4) * BSTR + n]);
            }
#pragma unroll
            for (int ma = 0; ma < 4; ++ma)
#pragma unroll
                for (int na = 0; na < 4; ++na)
                    MMA_TF32(acc[ma][na], a[ma], bf[na]);
        }
        __syncthreads();
    }

    // epilogue
#pragma unroll
    for (int ma = 0; ma < 4; ++ma) {
        const int r0 = bm + wm * 64 + ma * 16 + gid;
#pragma unroll
        for (int na = 0; na < 4; ++na) {
            const int cc = bn + wn * 32 + na * 8 + 2 * tig;
            const float b0 = bias[cc], b1 = bias[cc + 1];
            float v0 = acc[ma][na][0] + b0, v1 = acc[ma][na][1] + b1;
            float v2 = acc[ma][na][2] + b0, v3 = acc[ma][na][3] + b1;
            if (res) {
                float2 ra = *(const float2*)&res[(size_t)r0 * N + cc];
                float2 rb = *(const float2*)&res[(size_t)(r0 + 8) * N + cc];
                v0 += ra.x; v1 += ra.y; v2 += rb.x; v3 += rb.y;
            }
            if (round_out) {
                v0 = tf32r(v0); v1 = tf32r(v1);
                v2 = tf32r(v2); v3 = tf32r(v3);
            }
            *(float2*)&C[(size_t)r0 * N + cc] = make_float2(v0, v1);
            *(float2*)&C[(size_t)(r0 + 8) * N + cc] = make_float2(v2, v3);
        }
    }
}

// ---------------- Flash attention, tf32 tensor cores -------------------------
// q/k/v values already tf32-exact. 128 threads (4 warps), q-tile 64.
// Warp w owns rows [16w,16w+16) and all 64 cols -> quad-shuffle softmax.
#define AT_PAD 72
#define FLASH_SMEM (4 * 64 * AT_PAD * 4)

__global__ __launch_bounds__(128) void flash_tf32(
    const float* __restrict__ q, const float* __restrict__ k,
    const float* __restrict__ v, float* __restrict__ o)
{
    extern __shared__ float smf[];
    float* Qs = smf;                      // [64][72] (m x k)
    float* Ks = smf + 64 * AT_PAD;        // [64][72] (n x k)
    float* Vs = smf + 2 * 64 * AT_PAD;    // [64][72] (k x n)
    float* Ps = smf + 3 * 64 * AT_PAD;    // [64][72] (m x k)

    const int tid = threadIdx.x;
    const int warp = tid >> 5, lane = tid & 31;
    const int gid = lane >> 2, tig = lane & 3;
    const int qt = blockIdx.x, h = blockIdx.y, b = blockIdx.z;
    const int q0 = qt * 64;
    const size_t base = (size_t)b * SQ * DM + (size_t)h * HD;

    // load Q tile (scale by 0.125 = 2^-3, exact, keeps tf32-ness)
    {
        const int r = tid >> 1, c0 = (tid & 1) * 32;
        const float* qp = q + base + (size_t)(q0 + r) * DM + c0;
        float* dst = Qs + r * AT_PAD + c0;
#pragma unroll
        for (int u = 0; u < 8; ++u) {
            float4 t = *(const float4*)(qp + 4 * u);
            t.x *= 0.125f; t.y *= 0.125f; t.z *= 0.125f; t.w *= 0.125f;
            *(float4*)(dst + 4 * u) = t;
        }
    }

    float m0 = -1e30f, m1 = -1e30f, l0 = 0.f, l1 = 0.f;
    float ob[8][4];
#pragma unroll
    for (int na = 0; na < 8; ++na)
#pragma unroll
        for (int j = 0; j < 4; ++j) ob[na][j] = 0.f;

    const int rloc0 = warp * 16 + gid;    // local row (and +8)

    for (int kt = 0; kt <= qt; ++kt) {
        __syncthreads();
        {
            const int r = tid >> 1, c0 = (tid & 1) * 32;
            const float* kp = k + base + (size_t)(kt * 64 + r) * DM + c0;
            const float* vp = v + base + (size_t)(kt * 64 + r) * DM + c0;
            float* kd = Ks + r * AT_PAD + c0;
            float* vd = Vs + r * AT_PAD + c0;
#pragma unroll
            for (int u = 0; u < 8; ++u) {
                *(float4*)(kd + 4 * u) = *(const float4*)(kp + 4 * u);
                *(float4*)(vd + 4 * u) = *(const float4*)(vp + 4 * u);
            }
        }
        __syncthreads();

        // S = Q @ K^T via mma
        float s[8][4];
#pragma unroll
        for (int na = 0; na < 8; ++na)
#pragma unroll
            for (int j = 0; j < 4; ++j) s[na][j] = 0.f;

#pragma unroll
        for (int kk = 0; kk < 8; ++kk) {
            const int c = kk * 8 + tig;
            uint32_t a[4];
            a[0] = __float_as_uint(Qs[rloc0 * AT_PAD + c]);
            a[1] = __float_as_uint(Qs[(rloc0 + 8) * AT_PAD + c]);
            a[2] = __float_as_uint(Qs[rloc0 * AT_PAD + c + 4]);
            a[3] = __float_as_uint(Qs[(rloc0 + 8) * AT_PAD + c + 4]);
#pragma unroll
            for (int na = 0; na < 8; ++na) {
                uint32_t bf[2];
                bf[0] = __float_as_uint(Ks[(na * 8 + gid) * AT_PAD + c]);
                bf[1] = __float_as_uint(Ks[(na * 8 + gid) * AT_PAD + c + 4]);
                MMA_TF32(s[na], a, bf);
            }
        }

        if (kt == qt) {   // causal mask on diagonal tile (local coords)
#pragma unroll
            for (int na = 0; na < 8; ++na) {
                const int c0 = na * 8 + 2 * tig, c1 = c0 + 1;
                if (c0 > rloc0)     s[na][0] = -1e30f;
                if (c1 > rloc0)     s[na][1] = -1e30f;
                if (c0 > rloc0 + 8) s[na][2] = -1e30f;
                if (c1 > rloc0 + 8) s[na][3] = -1e30f;
            }
        }

        // online softmax: rows rloc0 (regs 0,1) and rloc0+8 (regs 2,3)
        float rm0 = -1e30f, rm1 = -1e30f;
#pragma unroll
        for (int na = 0; na < 8; ++na) {
            rm0 = fmaxf(rm0, fmaxf(s[na][0], s[na][1]));
            rm1 = fmaxf(rm1, fmaxf(s[na][2], s[na][3]));
        }
        rm0 = fmaxf(rm0, __shfl_xor_sync(0xffffffffu, rm0, 1));
        rm0 = fmaxf(rm0, __shfl_xor_sync(0xffffffffu, rm0, 2));
        rm1 = fmaxf(rm1, __shfl_xor_sync(0xffffffffu, rm1, 1));
        rm1 = fmaxf(rm1, __shfl_xor_sync(0xffffffffu, rm1, 2));

        const float mn0 = fmaxf(m0, rm0), mn1 = fmaxf(m1, rm1);
        const float al0 = __expf(m0 - mn0), al1 = __expf(m1 - mn1);
        float rs0 = 0.f, rs1 = 0.f;
#pragma unroll
        for (int na = 0; na < 8; ++na) {
            s[na][0] = __expf(s[na][0] - mn0);
            s[na][1] = __expf(s[na][1] - mn0);
            s[na][2] = __expf(s[na][2] - mn1);
            s[na][3] = __expf(s[na][3] - mn1);
            rs0 += s[na][0] + s[na][1];
            rs1 += s[na][2] + s[na][3];
            ob[na][0] *= al0; ob[na][1] *= al0;
            ob[na][2] *= al1; ob[na][3] *= al1;
        }
        rs0 += __shfl_xor_sync(0xffffffffu, rs0, 1);
        rs0 += __shfl_xor_sync(0xffffffffu, rs0, 2);
        rs1 += __shfl_xor_sync(0xffffffffu, rs1, 1);
        rs1 += __shfl_xor_sync(0xffffffffu, rs1, 2);
        l0 = l0 * al0 + rs0; m0 = mn0;
        l1 = l1 * al1 + rs1; m1 = mn1;

        // stage P (tf32-rounded) — warp-local rows only
#pragma unroll
        for (int na = 0; na < 8; ++na) {
            *(float2*)&Ps[rloc0 * AT_PAD + na * 8 + 2 * tig] =
                make_float2(tf32r(s[na][0]), tf32r(s[na][1]));
            *(float2*)&Ps[(rloc0 + 8) * AT_PAD + na * 8 + 2 * tig] =
                make_float2(tf32r(s[na][2]), tf32r(s[na][3]));
        }
        __syncwarp();

        // O += P @ V
#pragma unroll
        for (int kk = 0; kk < 8; ++kk) {
            const int c = kk * 8 + tig;
            uint32_t a[4];
            a[0] = __float_as_uint(Ps[rloc0 * AT_PAD + c]);
            a[1] = __float_as_uint(Ps[(rloc0 + 8) * AT_PAD + c]);
            a[2] = __float_as_uint(Ps[rloc0 * AT_PAD + c + 4]);
            a[3] = __float_as_uint(Ps[(rloc0 + 8) * AT_PAD + c + 4]);
#pragma unroll
            for (int na = 0; na < 8; ++na) {
                uint32_t bf[2];
                bf[0] = __float_as_uint(Vs[c * AT_PAD + na * 8 + gid]);
                bf[1] = __float_as_uint(Vs[(c + 4) * AT_PAD + na * 8 + gid]);
                MMA_TF32(ob[na], a, bf);
            }
        }
        __syncwarp();
    }

    // epilogue (tf32-round O so the proj GEMM needs no cvt)
    const float inv0 = 1.f / l0, inv1 = 1.f / l1;
    const int gr0 = q0 + rloc0, gr1 = gr0 + 8;
#pragma unroll
    for (int na = 0; na < 8; ++na) {
        const int d = na * 8 + 2 * tig;
        *(float2*)&o[base + (size_t)gr0 * DM + d] =
            make_float2(tf32r(ob[na][0] * inv0), tf32r(ob[na][1] * inv0));
        *(float2*)&o[base + (size_t)gr1 * DM + d] =
            make_float2(tf32r(ob[na][2] * inv1), tf32r(ob[na][3] * inv1));
    }
}

// ---------------- LayerNorm ---------------------------------------------------
__global__ __launch_bounds__(256) void ln_kernel(
    const float* __restrict__ y, const float* __restrict__ g,
    const float* __restrict__ bta, float* __restrict__ out)
{
    const int row = blockIdx.x;
    const int tid = threadIdx.x;
    const float* yr = y + (size_t)row * DM;

    float4 vv = *(const float4*)(yr + tid * 4);
    float s  = vv.x + vv.y + vv.z + vv.w;
    float sq = vv.x * vv.x + vv.y * vv.y + vv.z * vv.z + vv.w * vv.w;

#pragma unroll
    for (int off = 16; off > 0; off >>= 1) {
        s  += __shfl_xor_sync(0xffffffffu, s, off);
        sq += __shfl_xor_sync(0xffffffffu, sq, off);
    }
    __shared__ float ssum[8], ssq[8];
    if ((tid & 31) == 0) { ssum[tid >> 5] = s; ssq[tid >> 5] = sq; }
    __syncthreads();
    __shared__ float mu_s, rs_s;
    if (tid == 0) {
        float ts = 0.f, tq = 0.f;
#pragma unroll
        for (int i = 0; i < 8; ++i) { ts += ssum[i]; tq += ssq[i]; }
        float mu = ts * (1.f / DM);
        float var = tq * (1.f / DM) - mu * mu;
        mu_s = mu;
        rs_s = rsqrtf(var + 1e-5f);
    }
    __syncthreads();
    float mu = mu_s, rstd = rs_s;

    float4 gg = *(const float4*)(g + tid * 4);
    float4 bb = *(const float4*)(bta + tid * 4);
    float4 o;
    o.x = (vv.x - mu) * rstd * gg.x + bb.x;
    o.y = (vv.y - mu) * rstd * gg.y + bb.y;
    o.z = (vv.z - mu) * rstd * gg.z + bb.z;
    o.w = (vv.w - mu) * rstd * gg.w + bb.w;
    *(float4*)&out[(size_t)row * DM + tid * 4] = o;
}

// ---------------- launch ------------------------------------------------------
extern "C" void kernel_launch(void* const* d_in, const int* in_sizes, int n_in,
                              void* d_out, int out_size)
{
    const float* x  = (const float*)d_in[0];
    const float* Wq = (const float*)d_in[1];
    const float* bq = (const float*)d_in[2];
    const float* Wk = (const float*)d_in[3];
    const float* bk = (const float*)d_in[4];
    const float* Wv = (const float*)d_in[5];
    const float* bv = (const float*)d_in[6];
    const float* Wp = (const float*)d_in[7];
    const float* bp = (const float*)d_in[8];
    const float* lg = (const float*)d_in[9];
    const float* lb = (const float*)d_in[10];
    float* out = (float*)d_out;

    float *q, *k, *v, *attn, *y, *xr, *wq, *wk, *wv, *wp;
    cudaGetSymbolAddress((void**)&q, g_q);
    cudaGetSymbolAddress((void**)&k, g_k);
    cudaGetSymbolAddress((void**)&v, g_v);
    cudaGetSymbolAddress((void**)&attn, g_attn);
    cudaGetSymbolAddress((void**)&y, g_y);
    cudaGetSymbolAddress((void**)&xr, g_xr);
    cudaGetSymbolAddress((void**)&wq, g_wq);
    cudaGetSymbolAddress((void**)&wk, g_wk);
    cudaGetSymbolAddress((void**)&wv, g_wv);
    cudaGetSymbolAddress((void**)&wp, g_wp);

    // pre-round inputs to tf32 values (rna, unbiased)
    {
        int n4x = MROWS * DM / 4;
        int n4w = DM * DM / 4;
        round_tf32_k<<<(n4x + 255) / 256, 256>>>(x, xr, n4x);
        round_tf32_k<<<(n4w + 255) / 256, 256>>>(Wq, wq, n4w);
        round_tf32_k<<<(n4w + 255) / 256, 256>>>(Wk, wk, n4w);
        round_tf32_k<<<(n4w + 255) / 256, 256>>>(Wv, wv, n4w);
        round_tf32_k<<<(n4w + 255) / 256, 256>>>(Wp, wp, n4w);
    }

    cudaFuncSetAttribute(gemm_tf32, cudaFuncAttributeMaxDynamicSharedMemorySize,
                         GEMM_SMEM);
    cudaFuncSetAttribute(flash_tf32, cudaFuncAttributeMaxDynamicSharedMemorySize,
                         FLASH_SMEM);

    dim3 gg(DM / GBN, MROWS / GBM);  // (8, 64)
    gemm_tf32<<<gg, 256, GEMM_SMEM>>>(xr, wq, bq, nullptr, q, DM, DM, 1);
    gemm_tf32<<<gg, 256, GEMM_SMEM>>>(xr, wk, bk, nullptr, k, DM, DM, 1);
    gemm_tf32<<<gg, 256, GEMM_SMEM>>>(xr, wv, bv, nullptr, v, DM, DM, 1);

    flash_tf32<<<dim3(SQ / 64, NH, BZ), 128, FLASH_SMEM>>>(q, k, v, attn);

    gemm_tf32<<<gg, 256, GEMM_SMEM>>>(attn, wp, bp, x, y, DM, DM, 0);
    ln_kernel<<<MROWS, 256>>>(y, lg, lb, out);
}

// round 4
// speedup vs baseline: 5.8418x; 2.7722x over previous
#include <cuda_runtime.h>
#include <cuda_bf16.h>
#include <math.h>
#include <stdint.h>

// Problem dims (fixed)
#define BZ 4
#define SQ 2048
#define DM 1024
#define NH 16
#define HD 64
#define MROWS (BZ * SQ)   // 8192

// ---------------- scratch (device globals) -----------------------------------
__device__ __nv_bfloat16 g_xb[(size_t)MROWS * DM];
__device__ __nv_bfloat16 g_qb[(size_t)MROWS * DM];
__device__ __nv_bfloat16 g_kb[(size_t)MROWS * DM];
__device__ __nv_bfloat16 g_vb[(size_t)MROWS * DM];
__device__ __nv_bfloat16 g_ab[(size_t)MROWS * DM];
__device__ __nv_bfloat16 g_wqb[(size_t)DM * DM];
__device__ __nv_bfloat16 g_wkb[(size_t)DM * DM];
__device__ __nv_bfloat16 g_wvb[(size_t)DM * DM];
__device__ __nv_bfloat16 g_wpb[(size_t)DM * DM];
__device__ float g_y[(size_t)MROWS * DM];

// ---------------- helpers ----------------------------------------------------
__device__ __forceinline__ uint32_t smem_u32(const void* p) {
    return (uint32_t)__cvta_generic_to_shared(p);
}
__device__ __forceinline__ uint32_t pk(float a, float b) {
    __nv_bfloat162 h = __floats2bfloat162_rn(a, b);
    return *(uint32_t*)&h;
}

#define CP_ASYNC16(dst_u32, src_ptr)                                       \
    asm volatile("cp.async.ca.shared.global [%0], [%1], 16;\n" ::          \
                 "r"(dst_u32), "l"(src_ptr))

#define LDSM4(r0, r1, r2, r3, a)                                           \
    asm volatile("ldmatrix.sync.aligned.m8n8.x4.shared.b16 "               \
                 "{%0,%1,%2,%3}, [%4];"                                    \
                 : "=r"(r0), "=r"(r1), "=r"(r2), "=r"(r3) : "r"(a))

#define LDSM4T(r0, r1, r2, r3, a)                                          \
    asm volatile("ldmatrix.sync.aligned.m8n8.x4.trans.shared.b16 "         \
                 "{%0,%1,%2,%3}, [%4];"                                    \
                 : "=r"(r0), "=r"(r1), "=r"(r2), "=r"(r3) : "r"(a))

#define MMAB(d, a, b0v, b1v)                                               \
    asm volatile(                                                          \
        "mma.sync.aligned.m16n8k16.row.col.f32.bf16.bf16.f32 "             \
        "{%0,%1,%2,%3}, {%4,%5,%6,%7}, {%8,%9}, {%0,%1,%2,%3};\n"          \
        : "+f"((d)[0]), "+f"((d)[1]), "+f"((d)[2]), "+f"((d)[3])           \
        : "r"((a)[0]), "r"((a)[1]), "r"((a)[2]), "r"((a)[3]),              \
          "r"(b0v), "r"(b1v))

// ---------------- prep kernels ------------------------------------------------
__global__ __launch_bounds__(256) void cvt_bf16(
    const float* __restrict__ in, __nv_bfloat16* __restrict__ out, int n4)
{
    int i = blockIdx.x * blockDim.x + threadIdx.x;
    if (i < n4) {
        float4 t = ((const float4*)in)[i];
        uint2 o;
        o.x = pk(t.x, t.y);
        o.y = pk(t.z, t.w);
        ((uint2*)out)[i] = o;
    }
}

// Wt[n][k] = bf16(W[k][n])
__global__ __launch_bounds__(256) void wtrans_bf16(
    const float* __restrict__ W, __nv_bfloat16* __restrict__ Wt)
{
    __shared__ float t[32][33];
    const int n0 = blockIdx.x * 32, k0 = blockIdx.y * 32;
    const int tx = threadIdx.x, ty = threadIdx.y;  // 32 x 8
#pragma unroll
    for (int i = 0; i < 32; i += 8)
        t[ty + i][tx] = W[(size_t)(k0 + ty + i) * DM + n0 + tx];
    __syncthreads();
#pragma unroll
    for (int i = 0; i < 32; i += 8)
        Wt[(size_t)(n0 + ty + i) * DM + k0 + tx] =
            __float2bfloat16_rn(t[tx][ty + i]);
}

// ---------------- bf16 GEMM ---------------------------------------------------
// C[M,1024] = A[M,1024](bf16) @ Bt[n][k](bf16)^T + bias.
// Output: bf16 (Ob, scaled) or fp32 (Of, +res).
#define GBK 32
#define ASTR 40                    // bf16 per padded row
#define TILE_B (128 * ASTR * 2)    // 10240 bytes
#define STG_B (2 * TILE_B)         // 20480
#define NSTG 3
#define GEMM_SMEM (NSTG * STG_B)   // 61440

__global__ __launch_bounds__(256) void gemm_bf16(
    const __nv_bfloat16* __restrict__ A, const __nv_bfloat16* __restrict__ Bt,
    const float* __restrict__ bias, const float* __restrict__ res,
    __nv_bfloat16* __restrict__ Ob, float* __restrict__ Of, float oscale)
{
    extern __shared__ char smc[];
    const uint32_t sb = smem_u32(smc);

    const int tid = threadIdx.x;
    const int wid = tid >> 5, lane = tid & 31;
    const int gid = lane >> 2, tig = lane & 3;
    const int bm = blockIdx.y * 128;
    const int bn = blockIdx.x * 128;
    const int wm = wid >> 2, wn = wid & 3;

    const int r0c = tid >> 2;        // load row 0..63 (+64)
    const int c0c = tid & 3;         // 16B chunk in 32-col row
    const __nv_bfloat16* Ag = A + (size_t)bm * DM;
    const __nv_bfloat16* Bg = Bt + (size_t)bn * DM;

    float acc[4][4][4];
#pragma unroll
    for (int i = 0; i < 4; ++i)
#pragma unroll
        for (int j = 0; j < 4; ++j)
#pragma unroll
            for (int l = 0; l < 4; ++l) acc[i][j][l] = 0.f;

    auto load = [&](int t) {
        const uint32_t aB = sb + (t % NSTG) * STG_B;
        const uint32_t bB = aB + TILE_B;
        const int k0 = t * GBK + c0c * 8;
#pragma unroll
        for (int i = 0; i < 2; ++i) {
            const int r = r0c + 64 * i;
            CP_ASYNC16(aB + (r * ASTR + c0c * 8) * 2, Ag + (size_t)r * DM + k0);
            CP_ASYNC16(bB + (r * ASTR + c0c * 8) * 2, Bg + (size_t)r * DM + k0);
        }
        asm volatile("cp.async.commit_group;\n" ::);
    };

    load(0); load(1);
    const int NK = DM / GBK;  // 32

    const int a_row = wm * 64 + (lane & 7) + 8 * ((lane >> 3) & 1);
    const int a_sel = ((lane >> 4) & 1) * 16;   // byte col select
    const int b_rowo = (lane & 7) + 8 * ((lane >> 4) & 1);
    const int b_sel = ((lane >> 3) & 1) * 16;

    for (int t = 0; t < NK; ++t) {
        if (t + 1 < NK) asm volatile("cp.async.wait_group 1;\n" ::);
        else            asm volatile("cp.async.wait_group 0;\n" ::);
        __syncthreads();
        if (t + 2 < NK) load(t + 2);

        const uint32_t aB = sb + (t % NSTG) * STG_B;
        const uint32_t bB = aB + TILE_B;
#pragma unroll
        for (int kk = 0; kk < 2; ++kk) {
            uint32_t af[4][4], bf[4][2];
#pragma unroll
            for (int ma = 0; ma < 4; ++ma) {
                const uint32_t ad =
                    aB + (a_row + ma * 16) * (ASTR * 2) + kk * 32 + a_sel;
                LDSM4(af[ma][0], af[ma][1], af[ma][2], af[ma][3], ad);
            }
#pragma unroll
            for (int np = 0; np < 2; ++np) {
                const uint32_t bd =
                    bB + (wn * 32 + np * 16 + b_rowo) * (ASTR * 2) +
                    kk * 32 + b_sel;
                uint32_t r0, r1, r2, r3;
                LDSM4(r0, r1, r2, r3, bd);
                bf[2 * np][0] = r0; bf[2 * np][1] = r1;
                bf[2 * np + 1][0] = r2; bf[2 * np + 1][1] = r3;
            }
#pragma unroll
            for (int ma = 0; ma < 4; ++ma)
#pragma unroll
                for (int na = 0; na < 4; ++na)
                    MMAB(acc[ma][na], af[ma], bf[na][0], bf[na][1]);
        }
    }

    // epilogue straight from registers
#pragma unroll
    for (int ma = 0; ma < 4; ++ma) {
        const int r0 = bm + wm * 64 + ma * 16 + gid;
#pragma unroll
        for (int na = 0; na < 4; ++na) {
            const int c = bn + wn * 32 + na * 8 + 2 * tig;
            const float b0 = bias[c], b1 = bias[c + 1];
            float v0 = acc[ma][na][0] + b0, v1 = acc[ma][na][1] + b1;
            float v2 = acc[ma][na][2] + b0, v3 = acc[ma][na][3] + b1;
            if (Of) {
                float2 ra = *(const float2*)&res[(size_t)r0 * DM + c];
                float2 rb = *(const float2*)&res[(size_t)(r0 + 8) * DM + c];
                *(float2*)&Of[(size_t)r0 * DM + c] =
                    make_float2(v0 + ra.x, v1 + ra.y);
                *(float2*)&Of[(size_t)(r0 + 8) * DM + c] =
                    make_float2(v2 + rb.x, v3 + rb.y);
            } else {
                *(uint32_t*)&Ob[(size_t)r0 * DM + c] =
                    pk(v0 * oscale, v1 * oscale);
                *(uint32_t*)&Ob[(size_t)(r0 + 8) * DM + c] =
                    pk(v2 * oscale, v3 * oscale);
            }
        }
    }
}

// ---------------- Flash attention, bf16 mma, Q-tile 128 ----------------------
#define FSTR 72
#define FQ 0
#define FK (128 * FSTR)
#define FV (FK + 64 * FSTR)
#define FP (FV + 64 * FSTR)
#define FLASH_SMEM ((128 + 64 + 64 + 128) * FSTR * 2)   // 55296 B

__global__ __launch_bounds__(256) void flash_bf16(
    const __nv_bfloat16* __restrict__ q, const __nv_bfloat16* __restrict__ k,
    const __nv_bfloat16* __restrict__ v, __nv_bfloat16* __restrict__ o)
{
    extern __shared__ __nv_bfloat16 smb[];
    const uint32_t sb = smem_u32(smb);

    const int tid = threadIdx.x;
    const int warp = tid >> 5, lane = tid & 31;
    const int gid = lane >> 2, tig = lane & 3;
    const int bx = blockIdx.x, h = blockIdx.y, b = blockIdx.z;
    const int q0 = bx * 128;
    const size_t rowbase = (size_t)b * SQ;
    const size_t hoff = (size_t)h * HD;

    // load Q tile (bf16, pre-scaled at GEMM epilogue)
    {
        const int r = tid >> 1, hf = tid & 1;
        const uint4* src = (const uint4*)(q +
            ((rowbase + q0 + r) * DM + hoff + hf * 32));
        __nv_bfloat16* dst = smb + FQ + r * FSTR + hf * 32;
#pragma unroll
        for (int u = 0; u < 4; ++u)
            *(uint4*)(dst + u * 8) = src[u];
    }

    float m0 = -1e30f, m1 = -1e30f, l0 = 0.f, l1 = 0.f;
    float ob[8][4];
#pragma unroll
    for (int na = 0; na < 8; ++na)
#pragma unroll
        for (int j = 0; j < 4; ++j) ob[na][j] = 0.f;

    const int rloc0 = warp * 16 + gid;
    const int ktmax = 2 * bx + 1;

    // fragment address components (byte offsets)
    const int a_row = warp * 16 + (lane & 7) + 8 * ((lane >> 3) & 1);
    const int a_sel = ((lane >> 4) & 1) * 16;
    const uint32_t qa_base = sb + (FQ + a_row * FSTR) * 2 + a_sel;
    const uint32_t pa_base = sb + (FP + a_row * FSTR) * 2 + a_sel;
    const int b_rowo = (lane & 7) + 8 * ((lane >> 4) & 1);
    const int b_sel = ((lane >> 3) & 1) * 16;
    const int v_rowo = (lane & 7) + 8 * ((lane >> 3) & 1);
    const int v_sel = ((lane >> 4) & 1) * 16;

    for (int kt = 0; kt <= ktmax; ++kt) {
        __syncthreads();
        {
            const int r = tid >> 2, qd = tid & 3;
            const uint4* ks = (const uint4*)(k +
                ((rowbase + kt * 64 + r) * DM + hoff + qd * 16));
            const uint4* vs = (const uint4*)(v +
                ((rowbase + kt * 64 + r) * DM + hoff + qd * 16));
            __nv_bfloat16* kd = smb + FK + r * FSTR + qd * 16;
            __nv_bfloat16* vd = smb + FV + r * FSTR + qd * 16;
            *(uint4*)(kd) = ks[0];
            *(uint4*)(kd + 8) = ks[1];
            *(uint4*)(vd) = vs[0];
            *(uint4*)(vd + 8) = vs[1];
        }
        __syncthreads();

        // S = Q @ K^T
        float s[8][4];
#pragma unroll
        for (int na = 0; na < 8; ++na)
#pragma unroll
            for (int j = 0; j < 4; ++j) s[na][j] = 0.f;

#pragma unroll
        for (int kk = 0; kk < 4; ++kk) {
            uint32_t af[4];
            LDSM4(af[0], af[1], af[2], af[3], qa_base + kk * 32);
#pragma unroll
            for (int np = 0; np < 4; ++np) {
                const uint32_t bd = sb + (FK + (np * 16 + b_rowo) * FSTR) * 2 +
                                    kk * 32 + b_sel;
                uint32_t r0, r1, r2, r3;
                LDSM4(r0, r1, r2, r3, bd);
                MMAB(s[2 * np], af, r0, r1);
                MMAB(s[2 * np + 1], af, r2, r3);
            }
        }

        if (kt >= 2 * bx) {   // possibly-masked tiles
            const int row0 = q0 + rloc0, row1 = row0 + 8;
            const int cg0 = kt * 64;
#pragma unroll
            for (int na = 0; na < 8; ++na) {
                const int c0 = cg0 + na * 8 + 2 * tig, c1 = c0 + 1;
                if (c0 > row0) s[na][0] = -1e30f;
                if (c1 > row0) s[na][1] = -1e30f;
                if (c0 > row1) s[na][2] = -1e30f;
                if (c1 > row1) s[na][3] = -1e30f;
            }
        }

        // online softmax
        float rm0 = -1e30f, rm1 = -1e30f;
#pragma unroll
        for (int na = 0; na < 8; ++na) {
            rm0 = fmaxf(rm0, fmaxf(s[na][0], s[na][1]));
            rm1 = fmaxf(rm1, fmaxf(s[na][2], s[na][3]));
        }
        rm0 = fmaxf(rm0, __shfl_xor_sync(0xffffffffu, rm0, 1));
        rm0 = fmaxf(rm0, __shfl_xor_sync(0xffffffffu, rm0, 2));
        rm1 = fmaxf(rm1, __shfl_xor_sync(0xffffffffu, rm1, 1));
        rm1 = fmaxf(rm1, __shfl_xor_sync(0xffffffffu, rm1, 2));

        const float mn0 = fmaxf(m0, rm0), mn1 = fmaxf(m1, rm1);
        const float al0 = __expf(m0 - mn0), al1 = __expf(m1 - mn1);
        float rs0 = 0.f, rs1 = 0.f;
#pragma unroll
        for (int na = 0; na < 8; ++na) {
            s[na][0] = __expf(s[na][0] - mn0);
            s[na][1] = __expf(s[na][1] - mn0);
            s[na][2] = __expf(s[na][2] - mn1);
            s[na][3] = __expf(s[na][3] - mn1);
            rs0 += s[na][0] + s[na][1];
            rs1 += s[na][2] + s[na][3];
            ob[na][0] *= al0; ob[na][1] *= al0;
            ob[na][2] *= al1; ob[na][3] *= al1;
        }
        rs0 += __shfl_xor_sync(0xffffffffu, rs0, 1);
        rs0 += __shfl_xor_sync(0xffffffffu, rs0, 2);
        rs1 += __shfl_xor_sync(0xffffffffu, rs1, 1);
        rs1 += __shfl_xor_sync(0xffffffffu, rs1, 2);
        l0 = l0 * al0 + rs0; m0 = mn0;
        l1 = l1 * al1 + rs1; m1 = mn1;

        // stage P as bf16 (warp-local rows)
#pragma unroll
        for (int na = 0; na < 8; ++na) {
            *(uint32_t*)(smb + FP + rloc0 * FSTR + na * 8 + 2 * tig) =
                pk(s[na][0], s[na][1]);
            *(uint32_t*)(smb + FP + (rloc0 + 8) * FSTR + na * 8 + 2 * tig) =
                pk(s[na][2], s[na][3]);
        }
        __syncwarp();

        // O += P @ V
#pragma unroll
        for (int kat = 0; kat < 4; ++kat) {
            uint32_t pf[4];
            LDSM4(pf[0], pf[1], pf[2], pf[3], pa_base + kat * 32);
#pragma unroll
            for (int np = 0; np < 4; ++np) {
                const uint32_t vd = sb +
                    (FV + (kat * 16 + v_rowo) * FSTR) * 2 + np * 32 + v_sel;
                uint32_t r0, r1, r2, r3;
                LDSM4T(r0, r1, r2, r3, vd);
                MMAB(ob[2 * np], pf, r0, r1);
                MMAB(ob[2 * np + 1], pf, r2, r3);
            }
        }
        __syncwarp();
    }

    // output (bf16)
    const float inv0 = 1.f / l0, inv1 = 1.f / l1;
    const size_t gr0 = (rowbase + q0 + rloc0) * DM + hoff;
    const size_t gr1 = gr0 + 8 * DM;
#pragma unroll
    for (int na = 0; na < 8; ++na) {
        const int d = na * 8 + 2 * tig;
        *(uint32_t*)&o[gr0 + d] = pk(ob[na][0] * inv0, ob[na][1] * inv0);
        *(uint32_t*)&o[gr1 + d] = pk(ob[na][2] * inv1, ob[na][3] * inv1);
    }
}

// ---------------- LayerNorm ---------------------------------------------------
__global__ __launch_bounds__(256) void ln_kernel(
    const float* __restrict__ y, const float* __restrict__ g,
    const float* __restrict__ bta, float* __restrict__ out)
{
    const int row = blockIdx.x;
    const int tid = threadIdx.x;
    const float* yr = y + (size_t)row * DM;

    float4 vv = *(const float4*)(yr + tid * 4);
    float s  = vv.x + vv.y + vv.z + vv.w;
    float sq = vv.x * vv.x + vv.y * vv.y + vv.z * vv.z + vv.w * vv.w;

#pragma unroll
    for (int off = 16; off > 0; off >>= 1) {
        s  += __shfl_xor_sync(0xffffffffu, s, off);
        sq += __shfl_xor_sync(0xffffffffu, sq, off);
    }
    __shared__ float ssum[8], ssq[8];
    if ((tid & 31) == 0) { ssum[tid >> 5] = s; ssq[tid >> 5] = sq; }
    __syncthreads();
    __shared__ float mu_s, rs_s;
    if (tid == 0) {
        float ts = 0.f, tq = 0.f;
#pragma unroll
        for (int i = 0; i < 8; ++i) { ts += ssum[i]; tq += ssq[i]; }
        float mu = ts * (1.f / DM);
        float var = tq * (1.f / DM) - mu * mu;
        mu_s = mu;
        rs_s = rsqrtf(var + 1e-5f);
    }
    __syncthreads();
    const float mu = mu_s, rstd = rs_s;

    float4 gg = *(const float4*)(g + tid * 4);
    float4 bb = *(const float4*)(bta + tid * 4);
    float4 oo;
    oo.x = (vv.x - mu) * rstd * gg.x + bb.x;
    oo.y = (vv.y - mu) * rstd * gg.y + bb.y;
    oo.z = (vv.z - mu) * rstd * gg.z + bb.z;
    oo.w = (vv.w - mu) * rstd * gg.w + bb.w;
    *(float4*)&out[(size_t)row * DM + tid * 4] = oo;
}

// ---------------- launch ------------------------------------------------------
extern "C" void kernel_launch(void* const* d_in, const int* in_sizes, int n_in,
                              void* d_out, int out_size)
{
    const float* x  = (const float*)d_in[0];
    const float* Wq = (const float*)d_in[1];
    const float* bq = (const float*)d_in[2];
    const float* Wk = (const float*)d_in[3];
    const float* bk = (const float*)d_in[4];
    const float* Wv = (const float*)d_in[5];
    const float* bv = (const float*)d_in[6];
    const float* Wp = (const float*)d_in[7];
    const float* bp = (const float*)d_in[8];
    const float* lg = (const float*)d_in[9];
    const float* lb = (const float*)d_in[10];
    float* out = (float*)d_out;

    __nv_bfloat16 *xb, *qb, *kb, *vb, *ab, *wqb, *wkb, *wvb, *wpb;
    float* y;
    cudaGetSymbolAddress((void**)&xb, g_xb);
    cudaGetSymbolAddress((void**)&qb, g_qb);
    cudaGetSymbolAddress((void**)&kb, g_kb);
    cudaGetSymbolAddress((void**)&vb, g_vb);
    cudaGetSymbolAddress((void**)&ab, g_ab);
    cudaGetSymbolAddress((void**)&wqb, g_wqb);
    cudaGetSymbolAddress((void**)&wkb, g_wkb);
    cudaGetSymbolAddress((void**)&wvb, g_wvb);
    cudaGetSymbolAddress((void**)&wpb, g_wpb);
    cudaGetSymbolAddress((void**)&y, g_y);

    cvt_bf16<<<(MROWS * DM / 4 + 255) / 256, 256>>>(x, xb, MROWS * DM / 4);
    dim3 tg(32, 32), tb(32, 8);
    wtrans_bf16<<<tg, tb>>>(Wq, wqb);
    wtrans_bf16<<<tg, tb>>>(Wk, wkb);
    wtrans_bf16<<<tg, tb>>>(Wv, wvb);
    wtrans_bf16<<<tg, tb>>>(Wp, wpb);

    cudaFuncSetAttribute(gemm_bf16, cudaFuncAttributeMaxDynamicSharedMemorySize,
                         GEMM_SMEM);
    cudaFuncSetAttribute(flash_bf16, cudaFuncAttributeMaxDynamicSharedMemorySize,
                         FLASH_SMEM);

    dim3 gg(DM / 128, MROWS / 128);  // (8, 64)
    gemm_bf16<<<gg, 256, GEMM_SMEM>>>(xb, wqb, bq, nullptr, qb, nullptr, 0.125f);
    gemm_bf16<<<gg, 256, GEMM_SMEM>>>(xb, wkb, bk, nullptr, kb, nullptr, 1.f);
    gemm_bf16<<<gg, 256, GEMM_SMEM>>>(xb, wvb, bv, nullptr, vb, nullptr, 1.f);

    flash_bf16<<<dim3(SQ / 128, NH, BZ), 256, FLASH_SMEM>>>(qb, kb, vb, ab);

    gemm_bf16<<<gg, 256, GEMM_SMEM>>>(ab, wpb, bp, x, nullptr, y, 1.f);
    ln_kernel<<<MROWS, 256>>>(y, lg, lb, out);
}

// round 8
// speedup vs baseline: 6.5283x; 1.1175x over previous
#include <cuda_runtime.h>
#include <cuda_bf16.h>
#include <math.h>
#include <stdint.h>

// Problem dims (fixed)
#define BZ 4
#define SQ 2048
#define DM 1024
#define NH 16
#define HD 64
#define MROWS (BZ * SQ)   // 8192

#define QSCALE 0.18033688011112042f   // 0.125 * log2(e)

// ---------------- scratch (device globals) -----------------------------------
__device__ __nv_bfloat16 g_xb[(size_t)MROWS * DM];
__device__ __nv_bfloat16 g_qb[(size_t)MROWS * DM];
__device__ __nv_bfloat16 g_kb[(size_t)MROWS * DM];
__device__ __nv_bfloat16 g_vb[(size_t)MROWS * DM];
__device__ __nv_bfloat16 g_ab[(size_t)MROWS * DM];
__device__ __nv_bfloat16 g_wqb[(size_t)DM * DM];
__device__ __nv_bfloat16 g_wkb[(size_t)DM * DM];
__device__ __nv_bfloat16 g_wvb[(size_t)DM * DM];
__device__ __nv_bfloat16 g_wpb[(size_t)DM * DM];
__device__ float g_y[(size_t)MROWS * DM];

// ---------------- helpers ----------------------------------------------------
__device__ __forceinline__ uint32_t smem_u32(const void* p) {
    return (uint32_t)__cvta_generic_to_shared(p);
}
__device__ __forceinline__ uint32_t pk(float a, float b) {
    __nv_bfloat162 h = __floats2bfloat162_rn(a, b);
    return *(uint32_t*)&h;
}

#define CP_ASYNC16(dst_u32, src_ptr)                                       \
    asm volatile("cp.async.ca.shared.global [%0], [%1], 16;\n" ::          \
                 "r"(dst_u32), "l"(src_ptr))

#define LDSM4(r0, r1, r2, r3, a)                                           \
    asm volatile("ldmatrix.sync.aligned.m8n8.x4.shared.b16 "               \
                 "{%0,%1,%2,%3}, [%4];"                                    \
                 : "=r"(r0), "=r"(r1), "=r"(r2), "=r"(r3) : "r"(a))

#define LDSM4T(r0, r1, r2, r3, a)                                          \
    asm volatile("ldmatrix.sync.aligned.m8n8.x4.trans.shared.b16 "         \
                 "{%0,%1,%2,%3}, [%4];"                                    \
                 : "=r"(r0), "=r"(r1), "=r"(r2), "=r"(r3) : "r"(a))

#define MMAB(d, a, b0v, b1v)                                               \
    asm volatile(                                                          \
        "mma.sync.aligned.m16n8k16.row.col.f32.bf16.bf16.f32 "             \
        "{%0,%1,%2,%3}, {%4,%5,%6,%7}, {%8,%9}, {%0,%1,%2,%3};\n"          \
        : "+f"((d)[0]), "+f"((d)[1]), "+f"((d)[2]), "+f"((d)[3])           \
        : "r"((a)[0]), "r"((a)[1]), "r"((a)[2]), "r"((a)[3]),              \
          "r"(b0v), "r"(b1v))

// ---------------- prep kernels ------------------------------------------------
__global__ __launch_bounds__(256) void cvt_bf16(
    const float* __restrict__ in, __nv_bfloat16* __restrict__ out, int n4)
{
    int i = blockIdx.x * blockDim.x + threadIdx.x;
    if (i < n4) {
        float4 t = ((const float4*)in)[i];
        uint2 o;
        o.x = pk(t.x, t.y);
        o.y = pk(t.z, t.w);
        ((uint2*)out)[i] = o;
    }
}

// Wt[n][k] = bf16(W[k][n]) for 4 weights (blockIdx.z selects)
__global__ __launch_bounds__(256) void wtrans4_bf16(
    const float* __restrict__ W0, const float* __restrict__ W1,
    const float* __restrict__ W2, const float* __restrict__ W3,
    __nv_bfloat16* __restrict__ T0, __nv_bfloat16* __restrict__ T1,
    __nv_bfloat16* __restrict__ T2, __nv_bfloat16* __restrict__ T3)
{
    const int z = blockIdx.z;
    const float* W = (z == 0) ? W0 : (z == 1) ? W1 : (z == 2) ? W2 : W3;
    __nv_bfloat16* Wt = (z == 0) ? T0 : (z == 1) ? T1 : (z == 2) ? T2 : T3;

    __shared__ float t[32][33];
    const int n0 = blockIdx.x * 32, k0 = blockIdx.y * 32;
    const int tx = threadIdx.x, ty = threadIdx.y;  // 32 x 8
#pragma unroll
    for (int i = 0; i < 32; i += 8)
        t[ty + i][tx] = W[(size_t)(k0 + ty + i) * DM + n0 + tx];
    __syncthreads();
#pragma unroll
    for (int i = 0; i < 32; i += 8)
        Wt[(size_t)(n0 + ty + i) * DM + k0 + tx] =
            __float2bfloat16_rn(t[tx][ty + i]);
}

// ---------------- bf16 GEMM core ----------------------------------------------
#define GBK 32
#define ASTR 40
#define TILE_B (128 * ASTR * 2)
#define STG_B (2 * TILE_B)
#define NSTG 3
#define GEMM_SMEM (NSTG * STG_B)

__device__ __forceinline__ void gemm_core(
    const __nv_bfloat16* __restrict__ A, const __nv_bfloat16* __restrict__ Bt,
    const float* __restrict__ bias, const float* __restrict__ res,
    __nv_bfloat16* __restrict__ Ob, float* __restrict__ Of, float oscale,
    char* smc, int bm, int bn)
{
    const uint32_t sb = smem_u32(smc);
    const int tid = threadIdx.x;
    const int wid = tid >> 5, lane = tid & 31;
    const int gid = lane >> 2, tig = lane & 3;
    const int wm = wid >> 2, wn = wid & 3;

    const int r0c = tid >> 2;
    const int c0c = tid & 3;
    const __nv_bfloat16* Ag = A + (size_t)bm * DM;
    const __nv_bfloat16* Bg = Bt + (size_t)bn * DM;

    float acc[4][4][4];
#pragma unroll
    for (int i = 0; i < 4; ++i)
#pragma unroll
        for (int j = 0; j < 4; ++j)
#pragma unroll
            for (int l = 0; l < 4; ++l) acc[i][j][l] = 0.f;

    auto load = [&](int t) {
        const uint32_t aB = sb + (t % NSTG) * STG_B;
        const uint32_t bB = aB + TILE_B;
        const int k0 = t * GBK + c0c * 8;
#pragma unroll
        for (int i = 0; i < 2; ++i) {
            const int r = r0c + 64 * i;
            CP_ASYNC16(aB + (r * ASTR + c0c * 8) * 2, Ag + (size_t)r * DM + k0);
            CP_ASYNC16(bB + (r * ASTR + c0c * 8) * 2, Bg + (size_t)r * DM + k0);
        }
        asm volatile("cp.async.commit_group;\n" ::);
    };

    load(0); load(1);
    const int NK = DM / GBK;

    const int a_row = wm * 64 + (lane & 7) + 8 * ((lane >> 3) & 1);
    const int a_sel = ((lane >> 4) & 1) * 16;
    const int b_rowo = (lane & 7) + 8 * ((lane >> 4) & 1);
    const int b_sel = ((lane >> 3) & 1) * 16;

    for (int t = 0; t < NK; ++t) {
        if (t + 1 < NK) asm volatile("cp.async.wait_group 1;\n" ::);
        else            asm volatile("cp.async.wait_group 0;\n" ::);
        __syncthreads();
        if (t + 2 < NK) load(t + 2);

        const uint32_t aB = sb + (t % NSTG) * STG_B;
        const uint32_t bB = aB + TILE_B;
#pragma unroll
        for (int kk = 0; kk < 2; ++kk) {
            uint32_t af[4][4], bf[4][2];
#pragma unroll
            for (int ma = 0; ma < 4; ++ma) {
                const uint32_t ad =
                    aB + (a_row + ma * 16) * (ASTR * 2) + kk * 32 + a_sel;
                LDSM4(af[ma][0], af[ma][1], af[ma][2], af[ma][3], ad);
            }
#pragma unroll
            for (int np = 0; np < 2; ++np) {
                const uint32_t bd =
                    bB + (wn * 32 + np * 16 + b_rowo) * (ASTR * 2) +
                    kk * 32 + b_sel;
                uint32_t r0, r1, r2, r3;
                LDSM4(r0, r1, r2, r3, bd);
                bf[2 * np][0] = r0; bf[2 * np][1] = r1;
                bf[2 * np + 1][0] = r2; bf[2 * np + 1][1] = r3;
            }
#pragma unroll
            for (int ma = 0; ma < 4; ++ma)
#pragma unroll
                for (int na = 0; na < 4; ++na)
                    MMAB(acc[ma][na], af[ma], bf[na][0], bf[na][1]);
        }
    }

#pragma unroll
    for (int ma = 0; ma < 4; ++ma) {
        const int r0 = bm + wm * 64 + ma * 16 + gid;
#pragma unroll
        for (int na = 0; na < 4; ++na) {
            const int c = bn + wn * 32 + na * 8 + 2 * tig;
            const float b0 = bias[c], b1 = bias[c + 1];
            float v0 = acc[ma][na][0] + b0, v1 = acc[ma][na][1] + b1;
            float v2 = acc[ma][na][2] + b0, v3 = acc[ma][na][3] + b1;
            if (Of) {
                float2 ra = *(const float2*)&res[(size_t)r0 * DM + c];
                float2 rb = *(const float2*)&res[(size_t)(r0 + 8) * DM + c];
                *(float2*)&Of[(size_t)r0 * DM + c] =
                    make_float2(v0 + ra.x, v1 + ra.y);
                *(float2*)&Of[(size_t)(r0 + 8) * DM + c] =
                    make_float2(v2 + rb.x, v3 + rb.y);
            } else {
                *(uint32_t*)&Ob[(size_t)r0 * DM + c] =
                    pk(v0 * oscale, v1 * oscale);
                *(uint32_t*)&Ob[(size_t)(r0 + 8) * DM + c] =
                    pk(v2 * oscale, v3 * oscale);
            }
        }
    }
}

// fused QKV: blockIdx.z selects weight/bias/output
__global__ __launch_bounds__(256) void gemm_qkv(
    const __nv_bfloat16* __restrict__ A,
    const __nv_bfloat16* __restrict__ W0, const __nv_bfloat16* __restrict__ W1,
    const __nv_bfloat16* __restrict__ W2,
    const float* __restrict__ b0, const float* __restrict__ b1,
    const float* __restrict__ b2,
    __nv_bfloat16* __restrict__ O0, __nv_bfloat16* __restrict__ O1,
    __nv_bfloat16* __restrict__ O2)
{
    extern __shared__ char smc[];
    const int z = blockIdx.z;
    const __nv_bfloat16* Bt = (z == 0) ? W0 : (z == 1) ? W1 : W2;
    const float* bias = (z == 0) ? b0 : (z == 1) ? b1 : b2;
    __nv_bfloat16* Ob = (z == 0) ? O0 : (z == 1) ? O1 : O2;
    const float os = (z == 0) ? QSCALE : 1.f;
    gemm_core(A, Bt, bias, nullptr, Ob, nullptr, os, smc,
              blockIdx.y * 128, blockIdx.x * 128);
}

__global__ __launch_bounds__(256) void gemm_proj(
    const __nv_bfloat16* __restrict__ A, const __nv_bfloat16* __restrict__ Bt,
    const float* __restrict__ bias, const float* __restrict__ res,
    float* __restrict__ Of)
{
    extern __shared__ char smc[];
    gemm_core(A, Bt, bias, res, nullptr, Of, 1.f, smc,
              blockIdx.y * 128, blockIdx.x * 128);
}

// ---------------- Flash attention: bf16 mma, Q-tile 128, P in regs -----------
#define FSTR 72
#define FQ 0
#define FKV (128 * FSTR)
#define STGE (2 * 64 * FSTR)            // K + V per stage (bf16 elems)
#define FLASH_SMEM ((128 * FSTR + 2 * STGE) * 2)   // 55296 B

__global__ __launch_bounds__(256) void flash_bf16(
    const __nv_bfloat16* __restrict__ q, const __nv_bfloat16* __restrict__ k,
    const __nv_bfloat16* __restrict__ v, __nv_bfloat16* __restrict__ o)
{
    extern __shared__ __nv_bfloat16 smb[];
    const uint32_t sb = smem_u32(smb);

    const int tid = threadIdx.x;
    const int warp = tid >> 5, lane = tid & 31;
    const int gid = lane >> 2, tig = lane & 3;
    const int bx = blockIdx.x, h = blockIdx.y, b = blockIdx.z;
    const int q0 = bx * 128;
    const size_t rowbase = (size_t)b * SQ;
    const size_t hoff = (size_t)h * HD;

    const int kvr = tid >> 2, kvc = (tid & 3) * 16;
    auto loadkv = [&](int kt, int stage) {
        const __nv_bfloat16* kp =
            k + (rowbase + kt * 64 + kvr) * DM + hoff + kvc;
        const __nv_bfloat16* vp =
            v + (rowbase + kt * 64 + kvr) * DM + hoff + kvc;
        const uint32_t kd = sb + (FKV + stage * STGE + kvr * FSTR + kvc) * 2;
        const uint32_t vd = kd + 64 * FSTR * 2;
        CP_ASYNC16(kd, kp);
        CP_ASYNC16(kd + 16, kp + 8);
        CP_ASYNC16(vd, vp);
        CP_ASYNC16(vd + 16, vp + 8);
        asm volatile("cp.async.commit_group;\n" ::);
    };

    loadkv(0, 0);

    // load Q tile into smem
    {
        const int r = tid >> 1, hf = tid & 1;
        const uint4* src = (const uint4*)(q +
            ((rowbase + q0 + r) * DM + hoff + hf * 32));
        __nv_bfloat16* dst = smb + FQ + r * FSTR + hf * 32;
#pragma unroll
        for (int u = 0; u < 4; ++u)
            *(uint4*)(dst + u * 8) = src[u];
    }
    __syncthreads();

    // hoist Q fragments (held in regs for whole kernel)
    const int a_row = warp * 16 + (lane & 7) + 8 * ((lane >> 3) & 1);
    const int a_sel = ((lane >> 4) & 1) * 16;
    uint32_t afq[4][4];
    {
        const uint32_t qa_base = sb + (FQ + a_row * FSTR) * 2 + a_sel;
#pragma unroll
        for (int kk = 0; kk < 4; ++kk)
            LDSM4(afq[kk][0], afq[kk][1], afq[kk][2], afq[kk][3],
                  qa_base + kk * 32);
    }

    float m0 = -1e30f, m1 = -1e30f, l0 = 0.f, l1 = 0.f;
    float ob[8][4];
#pragma unroll
    for (int na = 0; na < 8; ++na)
#pragma unroll
        for (int j = 0; j < 4; ++j) ob[na][j] = 0.f;

    const int rloc0 = warp * 16 + gid;
    const int ktmax = 2 * bx + 1;

    const int b_rowo = (lane & 7) + 8 * ((lane >> 4) & 1);
    const int b_sel = ((lane >> 3) & 1) * 16;
    const int v_rowo = (lane & 7) + 8 * ((lane >> 3) & 1);
    const int v_sel = ((lane >> 4) & 1) * 16;

    for (int kt = 0; kt <= ktmax; ++kt) {
        if (kt + 1 <= ktmax) {
            loadkv(kt + 1, (kt + 1) & 1);
            asm volatile("cp.async.wait_group 1;\n" ::);
        } else {
            asm volatile("cp.async.wait_group 0;\n" ::);
        }
        __syncthreads();

        const uint32_t kbase = sb + (FKV + (kt & 1) * STGE) * 2;
        const uint32_t vbase = kbase + 64 * FSTR * 2;

        // S = Q @ K^T (logits already in log2 domain via QSCALE)
        float s[8][4];
#pragma unroll
        for (int na = 0; na < 8; ++na)
#pragma unroll
            for (int j = 0; j < 4; ++j) s[na][j] = 0.f;

#pragma unroll
        for (int kk = 0; kk < 4; ++kk) {
#pragma unroll
            for (int np = 0; np < 4; ++np) {
                const uint32_t bd = kbase +
                    (np * 16 + b_rowo) * (FSTR * 2) + kk * 32 + b_sel;
                uint32_t r0, r1, r2, r3;
                LDSM4(r0, r1, r2, r3, bd);
                MMAB(s[2 * np], afq[kk], r0, r1);
                MMAB(s[2 * np + 1], afq[kk], r2, r3);
            }
        }

        if (kt >= 2 * bx) {   // possibly-masked tiles
            const int row0 = q0 + rloc0, row1 = row0 + 8;
            const int cg0 = kt * 64;
#pragma unroll
            for (int na = 0; na < 8; ++na) {
                const int c0 = cg0 + na * 8 + 2 * tig, c1 = c0 + 1;
                if (c0 > row0) s[na][0] = -1e30f;
                if (c1 > row0) s[na][1] = -1e30f;
                if (c0 > row1) s[na][2] = -1e30f;
                if (c1 > row1) s[na][3] = -1e30f;
            }
        }

        // online softmax (base-2)
        float rm0 = -1e30f, rm1 = -1e30f;
#pragma unroll
        for (int na = 0; na < 8; ++na) {
            rm0 = fmaxf(rm0, fmaxf(s[na][0], s[na][1]));
            rm1 = fmaxf(rm1, fmaxf(s[na][2], s[na][3]));
        }
        rm0 = fmaxf(rm0, __shfl_xor_sync(0xffffffffu, rm0, 1));
        rm0 = fmaxf(rm0, __shfl_xor_sync(0xffffffffu, rm0, 2));
        rm1 = fmaxf(rm1, __shfl_xor_sync(0xffffffffu, rm1, 1));
        rm1 = fmaxf(rm1, __shfl_xor_sync(0xffffffffu, rm1, 2));

        const float mn0 = fmaxf(m0, rm0), mn1 = fmaxf(m1, rm1);
        const float al0 = exp2f(m0 - mn0), al1 = exp2f(m1 - mn1);
        float rs0 = 0.f, rs1 = 0.f;
#pragma unroll
        for (int na = 0; na < 8; ++na) {
            s[na][0] = exp2f(s[na][0] - mn0);
            s[na][1] = exp2f(s[na][1] - mn0);
            s[na][2] = exp2f(s[na][2] - mn1);
            s[na][3] = exp2f(s[na][3] - mn1);
            rs0 += s[na][0] + s[na][1];
            rs1 += s[na][2] + s[na][3];
            ob[na][0] *= al0; ob[na][1] *= al0;
            ob[na][2] *= al1; ob[na][3] *= al1;
        }
        rs0 += __shfl_xor_sync(0xffffffffu, rs0, 1);
        rs0 += __shfl_xor_sync(0xffffffffu, rs0, 2);
        rs1 += __shfl_xor_sync(0xffffffffu, rs1, 1);
        rs1 += __shfl_xor_sync(0xffffffffu, rs1, 2);
        l0 = l0 * al0 + rs0; m0 = mn0;
        l1 = l1 * al1 + rs1; m1 = mn1;

        // O += P @ V, P built directly from S registers (C->A layout match)
#pragma unroll
        for (int kat = 0; kat < 4; ++kat) {
            uint32_t pf[4];
            pf[0] = pk(s[2 * kat][0], s[2 * kat][1]);
            pf[1] = pk(s[2 * kat][2], s[2 * kat][3]);
            pf[2] = pk(s[2 * kat + 1][0], s[2 * kat + 1][1]);
            pf[3] = pk(s[2 * kat + 1][2], s[2 * kat + 1][3]);
#pragma unroll
            for (int np = 0; np < 4; ++np) {
                const uint32_t vd = vbase +
                    (kat * 16 + v_rowo) * (FSTR * 2) + np * 32 + v_sel;
                uint32_t r0, r1, r2, r3;
                LDSM4T(r0, r1, r2, r3, vd);
                MMAB(ob[2 * np], pf, r0, r1);
                MMAB(ob[2 * np + 1], pf, r2, r3);
            }
        }
        __syncthreads();   // all reads of stage (kt&1) done before next overwrite
    }

    // output (bf16)
    const float inv0 = 1.f / l0, inv1 = 1.f / l1;
    const size_t gr0 = (rowbase + q0 + rloc0) * DM + hoff;
    const size_t gr1 = gr0 + 8 * DM;
#pragma unroll
    for (int na = 0; na < 8; ++na) {
        const int d = na * 8 + 2 * tig;
        *(uint32_t*)&o[gr0 + d] = pk(ob[na][0] * inv0, ob[na][1] * inv0);
        *(uint32_t*)&o[gr1 + d] = pk(ob[na][2] * inv1, ob[na][3] * inv1);
    }
}

// ---------------- LayerNorm ---------------------------------------------------
__global__ __launch_bounds__(256) void ln_kernel(
    const float* __restrict__ y, const float* __restrict__ g,
    const float* __restrict__ bta, float* __restrict__ out)
{
    const int row = blockIdx.x;
    const int tid = threadIdx.x;
    const float* yr = y + (size_t)row * DM;

    float4 vv = *(const float4*)(yr + tid * 4);
    float s  = vv.x + vv.y + vv.z + vv.w;
    float sq = vv.x * vv.x + vv.y * vv.y + vv.z * vv.z + vv.w * vv.w;

#pragma unroll
    for (int off = 16; off > 0; off >>= 1) {
        s  += __shfl_xor_sync(0xffffffffu, s, off);
        sq += __shfl_xor_sync(0xffffffffu, sq, off);
    }
    __shared__ float ssum[8], ssq[8];
    if ((tid & 31) == 0) { ssum[tid >> 5] = s; ssq[tid >> 5] = sq; }
    __syncthreads();
    __shared__ float mu_s, rs_s;
    if (tid == 0) {
        float ts = 0.f, tq = 0.f;
#pragma unroll
        for (int i = 0; i < 8; ++i) { ts += ssum[i]; tq += ssq[i]; }
        float mu = ts * (1.f / DM);
        float var = tq * (1.f / DM) - mu * mu;
        mu_s = mu;
        rs_s = rsqrtf(var + 1e-5f);
    }
    __syncthreads();
    const float mu = mu_s, rstd = rs_s;

    float4 gg = *(const float4*)(g + tid * 4);
    float4 bb = *(const float4*)(bta + tid * 4);
    float4 oo;
    oo.x = (vv.x - mu) * rstd * gg.x + bb.x;
    oo.y = (vv.y - mu) * rstd * gg.y + bb.y;
    oo.z = (vv.z - mu) * rstd * gg.z + bb.z;
    oo.w = (vv.w - mu) * rstd * gg.w + bb.w;
    *(float4*)&out[(size_t)row * DM + tid * 4] = oo;
}

// ---------------- launch ------------------------------------------------------
extern "C" void kernel_launch(void* const* d_in, const int* in_sizes, int n_in,
                              void* d_out, int out_size)
{
    const float* x  = (const float*)d_in[0];
    const float* Wq = (const float*)d_in[1];
    const float* bq = (const float*)d_in[2];
    const float* Wk = (const float*)d_in[3];
    const float* bk = (const float*)d_in[4];
    const float* Wv = (const float*)d_in[5];
    const float* bv = (const float*)d_in[6];
    const float* Wp = (const float*)d_in[7];
    const float* bp = (const float*)d_in[8];
    const float* lg = (const float*)d_in[9];
    const float* lb = (const float*)d_in[10];
    float* out = (float*)d_out;

    __nv_bfloat16 *xb, *qb, *kb, *vb, *ab, *wqb, *wkb, *wvb, *wpb;
    float* y;
    cudaGetSymbolAddress((void**)&xb, g_xb);
    cudaGetSymbolAddress((void**)&qb, g_qb);
    cudaGetSymbolAddress((void**)&kb, g_kb);
    cudaGetSymbolAddress((void**)&vb, g_vb);
    cudaGetSymbolAddress((void**)&ab, g_ab);
    cudaGetSymbolAddress((void**)&wqb, g_wqb);
    cudaGetSymbolAddress((void**)&wkb, g_wkb);
    cudaGetSymbolAddress((void**)&wvb, g_wvb);
    cudaGetSymbolAddress((void**)&wpb, g_wpb);
    cudaGetSymbolAddress((void**)&y, g_y);

    cvt_bf16<<<(MROWS * DM / 4 + 255) / 256, 256>>>(x, xb, MROWS * DM / 4);
    wtrans4_bf16<<<dim3(32, 32, 4), dim3(32, 8)>>>(
        Wq, Wk, Wv, Wp, wqb, wkb, wvb, wpb);

    cudaFuncSetAttribute(gemm_qkv, cudaFuncAttributeMaxDynamicSharedMemorySize,
                         GEMM_SMEM);
    cudaFuncSetAttribute(gemm_proj, cudaFuncAttributeMaxDynamicSharedMemorySize,
                         GEMM_SMEM);
    cudaFuncSetAttribute(flash_bf16, cudaFuncAttributeMaxDynamicSharedMemorySize,
                         FLASH_SMEM);

    gemm_qkv<<<dim3(8, 64, 3), 256, GEMM_SMEM>>>(
        xb, wqb, wkb, wvb, bq, bk, bv, qb, kb, vb);

    flash_bf16<<<dim3(SQ / 128, NH, BZ), 256, FLASH_SMEM>>>(qb, kb, vb, ab);

    gemm_proj<<<dim3(8, 64), 256, GEMM_SMEM>>>(ab, wpb, bp, x, y);
    ln_kernel<<<MROWS, 256>>>(y, lg, lb, out);
}